// round 2
// baseline (speedup 1.0000x reference)
#include <cuda_runtime.h>
#include <cuda_bf16.h>
#include <cstdint>

// 3x3 cross-correlation, single channel, padding=1, stride=1, dilation=1.
// x: 4096x4096 fp32, weight: 9 fp32 (kh-major), bias: 1 fp32.
// out[i][j] = sum_{dr,dc} w[dr*3+dc] * x[i+dr-1][j+dc-1] + bias   (zero pad)
//
// Memory-bound design:
//  - CTA = 256 threads, computes a 128-wide x 32-tall output tile.
//  - Shared tile: 34 rows x 136-float stride. smem col s holds global col
//    (tile_x + s - 4). Interior (globals tile_x..tile_x+127) at cols 4..131
//    => float4 stores 16B-aligned. Left halo col 3, right halo col 132.
//  - Compute: output local col c needs smem cols c+3..c+5. Each thread does
//    4 outputs (c = tx*4..tx*4+3) -> needs cols tx*4+3..tx*4+8, fetched with
//    three aligned float4 LDS per input row.
//  - Stores: float4, fully coalesced.

#define N_IMG   4096
#define TILE_W  128
#define TILE_H  32
#define SM_H    (TILE_H + 2)   // 34
#define SM_W    136            // 4 pad + 128 interior + 1 halo + 3 pad; 544B stride

__global__ __launch_bounds__(256, 4)
void conv3x3_kernel(const float* __restrict__ x,
                    const float* __restrict__ w9,
                    const float* __restrict__ bias,
                    float* __restrict__ out)
{
    __shared__ __align__(16) float sm[SM_H][SM_W];

    const int tid    = threadIdx.x;            // 0..255
    const int tile_x = blockIdx.x * TILE_W;    // multiple of 128
    const int tile_y = blockIdx.y * TILE_H;    // multiple of 32

    // ---- fill interior: 34 rows x 32 float4 (smem cols 4..131) ----
    #pragma unroll
    for (int idx = tid; idx < SM_H * 32; idx += 256) {
        const int r = idx >> 5;          // 0..33
        const int v = idx & 31;          // 0..31
        const int grow = tile_y - 1 + r; // global row, may be -1 or 4096
        float4 val = make_float4(0.f, 0.f, 0.f, 0.f);
        if ((unsigned)grow < (unsigned)N_IMG) {
            val = *reinterpret_cast<const float4*>(
                      &x[(size_t)grow * N_IMG + tile_x + v * 4]);
        }
        *reinterpret_cast<float4*>(&sm[r][4 + v * 4]) = val;   // 16B-aligned
    }

    // ---- halos: left (smem col 3) and right (smem col 132), scalar ----
    if (tid < SM_H) {
        const int r = tid;
        const int grow = tile_y - 1 + r;
        const int gcol = tile_x - 1;
        float v = 0.f;
        if ((unsigned)grow < (unsigned)N_IMG && gcol >= 0)
            v = x[(size_t)grow * N_IMG + gcol];
        sm[r][3] = v;
    } else if (tid >= 64 && tid < 64 + SM_H) {
        const int r = tid - 64;
        const int grow = tile_y - 1 + r;
        const int gcol = tile_x + TILE_W;
        float v = 0.f;
        if ((unsigned)grow < (unsigned)N_IMG && gcol < N_IMG)
            v = x[(size_t)grow * N_IMG + gcol];
        sm[r][132] = v;
    }

    // ---- weights + bias (broadcast, tiny) ----
    float w[9];
    #pragma unroll
    for (int i = 0; i < 9; i++) w[i] = __ldg(&w9[i]);
    const float b = __ldg(&bias[0]);

    __syncthreads();

    const int tx = tid & 31;     // 0..31  -> 4-wide column group
    const int ty = tid >> 5;     // 0..7   -> row within 8-row stripe
    const int colbase = tx * 4;  // aligned smem col; need cols colbase+3..colbase+8

    #pragma unroll
    for (int rr = 0; rr < 4; rr++) {
        const int lrow = ty + rr * 8;   // output local row 0..31

        float rv[3][12];
        #pragma unroll
        for (int k = 0; k < 3; k++) {
            const float4 a = *reinterpret_cast<const float4*>(&sm[lrow + k][colbase    ]);
            const float4 bq= *reinterpret_cast<const float4*>(&sm[lrow + k][colbase + 4]);
            const float4 c = *reinterpret_cast<const float4*>(&sm[lrow + k][colbase + 8]);
            rv[k][0]=a.x;  rv[k][1]=a.y;  rv[k][2]=a.z;  rv[k][3]=a.w;
            rv[k][4]=bq.x; rv[k][5]=bq.y; rv[k][6]=bq.z; rv[k][7]=bq.w;
            rv[k][8]=c.x;  rv[k][9]=c.y;  rv[k][10]=c.z; rv[k][11]=c.w;
        }

        float4 o;
        float* op = &o.x;
        #pragma unroll
        for (int i = 0; i < 4; i++) {
            // output col colbase+i uses smem cols (colbase+i+3)..(+5)
            // relative index within rv: (i+3)..(i+5)
            float acc = b;
            acc = fmaf(w[0], rv[0][i + 3], acc);
            acc = fmaf(w[1], rv[0][i + 4], acc);
            acc = fmaf(w[2], rv[0][i + 5], acc);
            acc = fmaf(w[3], rv[1][i + 3], acc);
            acc = fmaf(w[4], rv[1][i + 4], acc);
            acc = fmaf(w[5], rv[1][i + 5], acc);
            acc = fmaf(w[6], rv[2][i + 3], acc);
            acc = fmaf(w[7], rv[2][i + 4], acc);
            acc = fmaf(w[8], rv[2][i + 5], acc);
            op[i] = acc;
        }

        const int grow = tile_y + lrow;
        *reinterpret_cast<float4*>(
            &out[(size_t)grow * N_IMG + tile_x + tx * 4]) = o;
    }
}

extern "C" void kernel_launch(void* const* d_in, const int* in_sizes, int n_in,
                              void* d_out, int out_size)
{
    const float* x    = (const float*)d_in[0];   // 4096*4096
    const float* w9   = (const float*)d_in[1];   // 9
    const float* bias = (const float*)d_in[2];   // 1
    float* out        = (float*)d_out;           // 4096*4096

    dim3 block(256, 1, 1);
    dim3 grid(N_IMG / TILE_W, N_IMG / TILE_H, 1);  // 32 x 128 = 4096 CTAs
    conv3x3_kernel<<<grid, block>>>(x, w9, bias, out);
}

// round 3
// speedup vs baseline: 1.1959x; 1.1959x over previous
#include <cuda_runtime.h>
#include <cuda_bf16.h>
#include <cstdint>

// 3x3 cross-correlation, 4096x4096 fp32, pad=1, stride=1.
// out[i][j] = sum_{dr,dc} w[dr*3+dc] * x[i+dr-1][j+dc-1] + bias
//
// No-smem register-rolling design:
//  - CTA = 256 threads = 8 warps. Warp w computes a 128-wide x R(=16)-row
//    output strip. Lane l owns 4 consecutive columns (tile_x + 4l .. +3).
//  - Stream R+2 input rows; per row: one aligned LDG.128 per lane, the +-1
//    horizontal neighbors come from __shfl (lanes 0/31 patch the strip edge
//    with a predicated scalar LDG). Each input row contributes to 3 output
//    rows via 3 rolling float4 accumulators; completed rows stored STG.128.
//  - Software prefetch: row i+1 load issued before row i compute.

#define N_IMG 4096
#define RPT   16            // output rows per warp
#define WARPS 8
#define TILE_H (RPT * WARPS)   // 128 rows per CTA
#define FULLMASK 0xFFFFFFFFu

struct RowData {
    float4 v;   // own 4 columns
    float  e;   // lane0: left-edge col, lane31: right-edge col, else unused
};

__device__ __forceinline__ RowData load_row(const float* __restrict__ x,
                                            int grow, int tile_x, int lane)
{
    RowData r;
    r.v = make_float4(0.f, 0.f, 0.f, 0.f);
    r.e = 0.f;
    if ((unsigned)grow < (unsigned)N_IMG) {
        const float* rowp = x + (size_t)grow * N_IMG;
        r.v = *reinterpret_cast<const float4*>(rowp + tile_x + lane * 4);
        if (lane == 0) {
            if (tile_x > 0) r.e = rowp[tile_x - 1];
        } else if (lane == 31) {
            if (tile_x + 128 < N_IMG) r.e = rowp[tile_x + 128];
        }
    }
    return r;
}

__global__ __launch_bounds__(256, 5)
void conv3x3_roll_kernel(const float* __restrict__ x,
                         const float* __restrict__ w9,
                         const float* __restrict__ bias,
                         float* __restrict__ out)
{
    const int tid    = threadIdx.x;
    const int lane   = tid & 31;
    const int warp   = tid >> 5;
    const int tile_x = blockIdx.x * 128;
    const int row0   = blockIdx.y * TILE_H + warp * RPT;  // first output row

    float w[9];
    #pragma unroll
    for (int i = 0; i < 9; i++) w[i] = __ldg(&w9[i]);
    const float b = __ldg(&bias[0]);

    const int colbase = tile_x + lane * 4;

    // rolling accumulators: accP = output row (i-1), accQ = output row i
    float4 accP = make_float4(b, b, b, b);
    float4 accQ = make_float4(b, b, b, b);

    RowData cur = load_row(x, row0 - 1, tile_x, lane);

    #pragma unroll 2
    for (int i = -1; i <= RPT; i++) {
        // prefetch next input row
        RowData nxt;
        if (i < RPT) nxt = load_row(x, row0 + i + 1, tile_x, lane);
        else { nxt.v = make_float4(0.f,0.f,0.f,0.f); nxt.e = 0.f; }

        // horizontal neighbors for cur
        float lf = __shfl_up_sync(FULLMASK, cur.v.w, 1);
        float rt = __shfl_down_sync(FULLMASK, cur.v.x, 1);
        if (lane == 0)  lf = cur.e;
        if (lane == 31) rt = cur.e;

        // shifted vectors: hl = cols (c-1..c+2), v = (c..c+3), hr = (c+1..c+4)
        const float hl0 = lf,      hl1 = cur.v.x, hl2 = cur.v.y, hl3 = cur.v.z;
        const float v0  = cur.v.x, v1  = cur.v.y, v2  = cur.v.z, v3  = cur.v.w;
        const float hr0 = cur.v.y, hr1 = cur.v.z, hr2 = cur.v.w, hr3 = rt;

        // weight-row horizontal convolutions of this input row
        float4 h0, h1, h2;
        h0.x = fmaf(w[0],hl0, fmaf(w[1],v0, w[2]*hr0));
        h0.y = fmaf(w[0],hl1, fmaf(w[1],v1, w[2]*hr1));
        h0.z = fmaf(w[0],hl2, fmaf(w[1],v2, w[2]*hr2));
        h0.w = fmaf(w[0],hl3, fmaf(w[1],v3, w[2]*hr3));

        h1.x = fmaf(w[3],hl0, fmaf(w[4],v0, w[5]*hr0));
        h1.y = fmaf(w[3],hl1, fmaf(w[4],v1, w[5]*hr1));
        h1.z = fmaf(w[3],hl2, fmaf(w[4],v2, w[5]*hr2));
        h1.w = fmaf(w[3],hl3, fmaf(w[4],v3, w[5]*hr3));

        h2.x = fmaf(w[6],hl0, fmaf(w[7],v0, w[8]*hr0));
        h2.y = fmaf(w[6],hl1, fmaf(w[7],v1, w[8]*hr1));
        h2.z = fmaf(w[6],hl2, fmaf(w[7],v2, w[8]*hr2));
        h2.w = fmaf(w[6],hl3, fmaf(w[7],v3, w[8]*hr3));

        // input row g contributes: h0 -> out g+1, h1 -> out g, h2 -> out g-1
        accP.x += h2.x; accP.y += h2.y; accP.z += h2.z; accP.w += h2.w;
        accQ.x += h1.x; accQ.y += h1.y; accQ.z += h1.z; accQ.w += h1.w;
        float4 accR = make_float4(b + h0.x, b + h0.y, b + h0.z, b + h0.w);

        if (i >= 1) {
            const int grow = row0 + i - 1;
            *reinterpret_cast<float4*>(out + (size_t)grow * N_IMG + colbase) = accP;
        }

        accP = accQ;
        accQ = accR;
        cur  = nxt;
    }
}

extern "C" void kernel_launch(void* const* d_in, const int* in_sizes, int n_in,
                              void* d_out, int out_size)
{
    const float* x    = (const float*)d_in[0];   // 4096*4096
    const float* w9   = (const float*)d_in[1];   // 9
    const float* bias = (const float*)d_in[2];   // 1
    float* out        = (float*)d_out;           // 4096*4096

    dim3 block(256, 1, 1);
    dim3 grid(N_IMG / 128, N_IMG / TILE_H, 1);   // 32 x 32 = 1024 CTAs
    conv3x3_roll_kernel<<<grid, block>>>(x, w9, bias, out);
}